// round 1
// baseline (speedup 1.0000x reference)
#include <cuda_runtime.h>
#include <cuda_bf16.h>

#define LL   512
#define BSZ  32
#define LP1  513
#define ROWF (3 * LP1)   // 1539 floats per (b, s, l) row
#define RCA  3.8f

// Scratch: Fa (12 floats, 3x4 row-major) + Fb (12 floats) per (b, l)
__device__ float g_F[BSZ * LL * 24];

// Affine 3x4 stored as r[0..8] row-major + t[9..11]. C = A @ B.
__device__ __forceinline__ void compose(const float* __restrict__ A,
                                        const float* __restrict__ B,
                                        float* __restrict__ C) {
#pragma unroll
    for (int i = 0; i < 3; i++) {
        const float a0 = A[i * 3 + 0], a1 = A[i * 3 + 1], a2 = A[i * 3 + 2];
        C[i * 3 + 0] = a0 * B[0] + a1 * B[3] + a2 * B[6];
        C[i * 3 + 1] = a0 * B[1] + a1 * B[4] + a2 * B[7];
        C[i * 3 + 2] = a0 * B[2] + a1 * B[5] + a2 * B[8];
        C[9 + i]     = a0 * B[9] + a1 * B[10] + a2 * B[11] + A[9 + i];
    }
}

// One block per batch. Kogge-Stone inclusive prefix product of the B frames,
// then per-l computation of Fa/Fb = Rprev @ (dB @ Minv).
__global__ __launch_bounds__(LL) void scan_kernel(const float* __restrict__ angles) {
    __shared__ float sm[LL * 13];   // stride 13: conflict-free (gcd(13,32)=1)
    const int b = blockIdx.x;
    const int l = threadIdx.x;

    const float alpha = angles[(b * 2 + 0) * LL + l];
    const float beta  = angles[(b * 2 + 1) * LL + l];
    float sa, ca, sb, cb;
    sincosf(alpha, &sa, &ca);
    sincosf(beta,  &sb, &cb);

    float M[12];
    M[0] = ca;  M[1] = -sa * cb; M[2] = sa * sb;
    M[3] = sa;  M[4] = ca * cb;  M[5] = -ca * sb;
    M[6] = 0.f; M[7] = sb;       M[8] = cb;
    M[9] = RCA * ca; M[10] = RCA * sa; M[11] = 0.f;

    float* mine = &sm[l * 13];
#pragma unroll
    for (int k = 0; k < 12; k++) mine[k] = M[k];
    __syncthreads();

#pragma unroll
    for (int off = 1; off < LL; off <<= 1) {
        float Lf[12];
        const bool act = (l >= off);
        if (act) {
            const float* p = &sm[(l - off) * 13];
#pragma unroll
            for (int k = 0; k < 12; k++) Lf[k] = p[k];
        }
        __syncthreads();
        if (act) {
            float T[12];
            compose(Lf, M, T);
#pragma unroll
            for (int k = 0; k < 12; k++) { M[k] = T[k]; mine[k] = T[k]; }
        }
        __syncthreads();
    }
    // sm now holds final inclusive products M_l for every l.

    // M_prev rotation (translation not needed: dB bottom row is zero)
    float Mp[12];
    if (l == 0) {
        Mp[0] = 1.f; Mp[1] = 0.f; Mp[2] = 0.f;
        Mp[3] = 0.f; Mp[4] = 1.f; Mp[5] = 0.f;
        Mp[6] = 0.f; Mp[7] = 0.f; Mp[8] = 1.f;
    } else {
        const float* p = &sm[(l - 1) * 13];
#pragma unroll
        for (int k = 0; k < 9; k++) Mp[k] = p[k];
    }
    Mp[9] = 0.f; Mp[10] = 0.f; Mp[11] = 0.f;

    // Minv = (R^T, -R^T t)
    float Mi[12];
    Mi[0] = M[0]; Mi[1] = M[3]; Mi[2] = M[6];
    Mi[3] = M[1]; Mi[4] = M[4]; Mi[5] = M[7];
    Mi[6] = M[2]; Mi[7] = M[5]; Mi[8] = M[8];
    Mi[9]  = -(Mi[0] * M[9] + Mi[1] * M[10] + Mi[2] * M[11]);
    Mi[10] = -(Mi[3] * M[9] + Mi[4] * M[10] + Mi[5] * M[11]);
    Mi[11] = -(Mi[6] * M[9] + Mi[7] * M[10] + Mi[8] * M[11]);

    // dB/da as affine (rows 0..1 nonzero, row 2 zero; t = (-R sa, R ca, 0))
    float Da[12];
    Da[0] = -sa; Da[1] = -ca * cb; Da[2] = ca * sb;
    Da[3] = ca;  Da[4] = -sa * cb; Da[5] = sa * sb;
    Da[6] = 0.f; Da[7] = 0.f;      Da[8] = 0.f;
    Da[9] = -RCA * sa; Da[10] = RCA * ca; Da[11] = 0.f;

    // dB/db as affine (t = 0)
    float Db[12];
    Db[0] = 0.f; Db[1] = sa * sb;  Db[2] = sa * cb;
    Db[3] = 0.f; Db[4] = -ca * sb; Db[5] = -ca * cb;
    Db[6] = 0.f; Db[7] = cb;       Db[8] = -sb;
    Db[9] = 0.f; Db[10] = 0.f;     Db[11] = 0.f;

    float G[12], Fa[12], Fb[12];
    compose(Da, Mi, G);
    compose(Mp, G, Fa);
    compose(Db, Mi, G);
    compose(Mp, G, Fb);

    float* o = &g_F[(b * LL + l) * 24];
#pragma unroll
    for (int i = 0; i < 3; i++) {
        o[i * 4 + 0] = Fa[i * 3 + 0];
        o[i * 4 + 1] = Fa[i * 3 + 1];
        o[i * 4 + 2] = Fa[i * 3 + 2];
        o[i * 4 + 3] = Fa[9 + i];
        o[12 + i * 4 + 0] = Fb[i * 3 + 0];
        o[12 + i * 4 + 1] = Fb[i * 3 + 1];
        o[12 + i * 4 + 2] = Fb[i * 3 + 2];
        o[12 + i * 4 + 3] = Fb[9 + i];
    }
}

// One block per (l, b). Streams both output rows (s=0: Fa, s=1: Fb) with
// coalesced scalar stores; coords cached in smem as float4 homogeneous points.
__global__ __launch_bounds__(256) void emit_kernel(const float* __restrict__ coords,
                                                   const int* __restrict__ lens,
                                                   float* __restrict__ out) {
    __shared__ float4 sC[LP1];
    __shared__ float sF[24];
    const int l   = blockIdx.x;
    const int b   = blockIdx.y;
    const int tid = threadIdx.x;

    for (int m = tid; m < LP1; m += 256) {
        const float* c = coords + (size_t)b * ROWF + m * 3;
        sC[m] = make_float4(c[0], c[1], c[2], 1.f);
    }
    if (tid < 24) sF[tid] = g_F[(b * LL + l) * 24 + tid];
    __syncthreads();

    const int len = lens[b];
    const bool rowAlive = (l < len);
    float* row0 = out + ((size_t)(b * 2 + 0) * LL + l) * ROWF;
    float* row1 = out + ((size_t)(b * 2 + 1) * LL + l) * ROWF;

    for (int e = tid; e < ROWF; e += 256) {
        const int m = e / 3;
        const int c = e - m * 3;
        const float4 p = sC[m];
        const bool on = rowAlive && (m > l) && (m <= len);
        float va = 0.f, vb = 0.f;
        if (on) {
            va = sF[c * 4 + 0] * p.x + sF[c * 4 + 1] * p.y +
                 sF[c * 4 + 2] * p.z + sF[c * 4 + 3];
            vb = sF[12 + c * 4 + 0] * p.x + sF[12 + c * 4 + 1] * p.y +
                 sF[12 + c * 4 + 2] * p.z + sF[12 + c * 4 + 3];
        }
        row0[e] = va;
        row1[e] = vb;
    }
}

extern "C" void kernel_launch(void* const* d_in, const int* in_sizes, int n_in,
                              void* d_out, int out_size) {
    const float* angles = (const float*)d_in[0];   // (32, 2, 512)
    const float* coords = (const float*)d_in[1];   // (32, 1539)
    const int*   lens   = (const int*)d_in[2];     // (32,)
    float* out = (float*)d_out;

    scan_kernel<<<BSZ, LL>>>(angles);
    emit_kernel<<<dim3(LL, BSZ), 256>>>(coords, lens, out);
}

// round 2
// speedup vs baseline: 1.0087x; 1.0087x over previous
#include <cuda_runtime.h>
#include <cuda_bf16.h>

#define LL   512
#define BSZ  32
#define LP1  513
#define ROWF (3 * LP1)   // 1539 floats per (b, s, l) row
#define RCA  3.8f

// Scratch: Fa (12 floats, 3x4 row-major) + Fb (12 floats) per (b, l)
__device__ float g_F[BSZ * LL * 24];

// Affine 3x4 stored as r[0..8] row-major + t[9..11]. C = A @ B.
__device__ __forceinline__ void compose(const float* __restrict__ A,
                                        const float* __restrict__ B,
                                        float* __restrict__ C) {
#pragma unroll
    for (int i = 0; i < 3; i++) {
        const float a0 = A[i * 3 + 0], a1 = A[i * 3 + 1], a2 = A[i * 3 + 2];
        C[i * 3 + 0] = a0 * B[0] + a1 * B[3] + a2 * B[6];
        C[i * 3 + 1] = a0 * B[1] + a1 * B[4] + a2 * B[7];
        C[i * 3 + 2] = a0 * B[2] + a1 * B[5] + a2 * B[8];
        C[9 + i]     = a0 * B[9] + a1 * B[10] + a2 * B[11] + A[9 + i];
    }
}

// One block per batch. Warp-shuffle inclusive prefix product over L=512,
// then per-l computation of Fa/Fb = Rprev @ (dB @ Minv).
__global__ __launch_bounds__(LL) void scan_kernel(const float* __restrict__ angles) {
    __shared__ float wTot[16][13];   // per-warp totals / prefixes (pad 13)
    const int b    = blockIdx.x;
    const int l    = threadIdx.x;
    const int w    = l >> 5;
    const int lane = l & 31;

    const float alpha = angles[(b * 2 + 0) * LL + l];
    const float beta  = angles[(b * 2 + 1) * LL + l];
    float sa, ca, sb, cb;
    sincosf(alpha, &sa, &ca);
    sincosf(beta,  &sb, &cb);

    float M[12];
    M[0] = ca;  M[1] = -sa * cb; M[2] = sa * sb;
    M[3] = sa;  M[4] = ca * cb;  M[5] = -ca * sb;
    M[6] = 0.f; M[7] = sb;       M[8] = cb;
    M[9] = RCA * ca; M[10] = RCA * sa; M[11] = 0.f;

    // --- warp-level inclusive scan (left-to-right product) ---
#pragma unroll
    for (int off = 1; off < 32; off <<= 1) {
        float Lf[12];
#pragma unroll
        for (int k = 0; k < 12; k++) Lf[k] = __shfl_up_sync(0xffffffffu, M[k], off);
        if (lane >= off) {
            float T[12];
            compose(Lf, M, T);
#pragma unroll
            for (int k = 0; k < 12; k++) M[k] = T[k];
        }
    }
    if (lane == 31) {
#pragma unroll
        for (int k = 0; k < 12; k++) wTot[w][k] = M[k];
    }
    __syncthreads();

    // --- scan the 16 warp totals (warp 0) ---
    if (w == 0) {
        float S[12];
        if (lane < 16) {
#pragma unroll
            for (int k = 0; k < 12; k++) S[k] = wTot[lane][k];
        } else {
            S[0] = 1.f; S[1] = 0.f; S[2] = 0.f;
            S[3] = 0.f; S[4] = 1.f; S[5] = 0.f;
            S[6] = 0.f; S[7] = 0.f; S[8] = 1.f;
            S[9] = 0.f; S[10] = 0.f; S[11] = 0.f;
        }
#pragma unroll
        for (int off = 1; off < 16; off <<= 1) {
            float Lf[12];
#pragma unroll
            for (int k = 0; k < 12; k++) Lf[k] = __shfl_up_sync(0xffffffffu, S[k], off);
            if (lane >= off && lane < 16) {
                float T[12];
                compose(Lf, S, T);
#pragma unroll
                for (int k = 0; k < 12; k++) S[k] = T[k];
            }
        }
        if (lane < 16) {
#pragma unroll
            for (int k = 0; k < 12; k++) wTot[lane][k] = S[k];
        }
    }
    __syncthreads();

    // --- apply block prefix: final inclusive product M_l ---
    float Fin[12];
    if (w > 0) {
        float P[12];
#pragma unroll
        for (int k = 0; k < 12; k++) P[k] = wTot[w - 1][k];
        compose(P, M, Fin);
    } else {
#pragma unroll
        for (int k = 0; k < 12; k++) Fin[k] = M[k];
    }

    // --- M_prev rotation via shfl of neighbor's final product ---
    float Mp[12];
#pragma unroll
    for (int k = 0; k < 9; k++) Mp[k] = __shfl_up_sync(0xffffffffu, Fin[k], 1);
    if (lane == 0) {
        if (w == 0) {
            Mp[0] = 1.f; Mp[1] = 0.f; Mp[2] = 0.f;
            Mp[3] = 0.f; Mp[4] = 1.f; Mp[5] = 0.f;
            Mp[6] = 0.f; Mp[7] = 0.f; Mp[8] = 1.f;
        } else {
#pragma unroll
            for (int k = 0; k < 9; k++) Mp[k] = wTot[w - 1][k];
        }
    }
    Mp[9] = 0.f; Mp[10] = 0.f; Mp[11] = 0.f;

    // Minv = (R^T, -R^T t)
    float Mi[12];
    Mi[0] = Fin[0]; Mi[1] = Fin[3]; Mi[2] = Fin[6];
    Mi[3] = Fin[1]; Mi[4] = Fin[4]; Mi[5] = Fin[7];
    Mi[6] = Fin[2]; Mi[7] = Fin[5]; Mi[8] = Fin[8];
    Mi[9]  = -(Mi[0] * Fin[9] + Mi[1] * Fin[10] + Mi[2] * Fin[11]);
    Mi[10] = -(Mi[3] * Fin[9] + Mi[4] * Fin[10] + Mi[5] * Fin[11]);
    Mi[11] = -(Mi[6] * Fin[9] + Mi[7] * Fin[10] + Mi[8] * Fin[11]);

    // dB/da as affine (row 2 zero)
    float Da[12];
    Da[0] = -sa; Da[1] = -ca * cb; Da[2] = ca * sb;
    Da[3] = ca;  Da[4] = -sa * cb; Da[5] = sa * sb;
    Da[6] = 0.f; Da[7] = 0.f;      Da[8] = 0.f;
    Da[9] = -RCA * sa; Da[10] = RCA * ca; Da[11] = 0.f;

    // dB/db as affine (t = 0)
    float Db[12];
    Db[0] = 0.f; Db[1] = sa * sb;  Db[2] = sa * cb;
    Db[3] = 0.f; Db[4] = -ca * sb; Db[5] = -ca * cb;
    Db[6] = 0.f; Db[7] = cb;       Db[8] = -sb;
    Db[9] = 0.f; Db[10] = 0.f;     Db[11] = 0.f;

    float G[12], Fa[12], Fb[12];
    compose(Da, Mi, G);
    compose(Mp, G, Fa);
    compose(Db, Mi, G);
    compose(Mp, G, Fb);

    float* o = &g_F[(b * LL + l) * 24];
#pragma unroll
    for (int i = 0; i < 3; i++) {
        o[i * 4 + 0] = Fa[i * 3 + 0];
        o[i * 4 + 1] = Fa[i * 3 + 1];
        o[i * 4 + 2] = Fa[i * 3 + 2];
        o[i * 4 + 3] = Fa[9 + i];
        o[12 + i * 4 + 0] = Fb[i * 3 + 0];
        o[12 + i * 4 + 1] = Fb[i * 3 + 1];
        o[12 + i * 4 + 2] = Fb[i * 3 + 2];
        o[12 + i * 4 + 3] = Fb[9 + i];
    }
}

// One block per (4 l-values, b). Phase 1 computes per-m values into smem
// (shift-staged so phase 2 is aligned float4 copies). 1539 = 3 + 4*384.
__global__ __launch_bounds__(256) void emit_kernel(const float* __restrict__ coords,
                                                   const int* __restrict__ lens,
                                                   float* __restrict__ out) {
    __shared__ float4 sC[LP1];
    __shared__ __align__(16) float sV[2][1544];
    __shared__ float sFs[24];
    const int b   = blockIdx.y;
    const int l0  = blockIdx.x << 2;
    const int tid = threadIdx.x;

    for (int m = tid; m < LP1; m += 256) {
        const float* c = coords + (size_t)b * ROWF + m * 3;
        sC[m] = make_float4(c[0], c[1], c[2], 1.f);
    }
    const int len = lens[b];

#pragma unroll 1
    for (int dl = 0; dl < 4; dl++) {
        const int l = l0 + dl;
        if (tid < 24) sFs[tid] = g_F[(b * LL + l) * 24 + tid];
        __syncthreads();   // sC/sFs ready; previous phase-2 done with sV

        float Fr[24];
#pragma unroll
        for (int k = 0; k < 24; k++) Fr[k] = sFs[k];

        const int  ao    = (3 * l) & 3;        // row base mod 4
        const int  head  = (4 - ao) & 3;       // scalars before first aligned vec4
        const bool alive = (l < len);

        // Phase 1: per-m compute, staged into smem at shift ao
        for (int m = tid; m < LP1; m += 256) {
            const float4 p = sC[m];
            const bool on = alive && (m > l) && (m <= len);
            float a0 = 0.f, a1 = 0.f, a2 = 0.f, b0 = 0.f, b1 = 0.f, b2 = 0.f;
            if (on) {
                a0 = Fr[0]  * p.x + Fr[1]  * p.y + Fr[2]  * p.z + Fr[3];
                a1 = Fr[4]  * p.x + Fr[5]  * p.y + Fr[6]  * p.z + Fr[7];
                a2 = Fr[8]  * p.x + Fr[9]  * p.y + Fr[10] * p.z + Fr[11];
                b0 = Fr[12] * p.x + Fr[13] * p.y + Fr[14] * p.z + Fr[15];
                b1 = Fr[16] * p.x + Fr[17] * p.y + Fr[18] * p.z + Fr[19];
                b2 = Fr[20] * p.x + Fr[21] * p.y + Fr[22] * p.z + Fr[23];
            }
            const int s = ao + 3 * m;
            sV[0][s]     = a0; sV[0][s + 1] = a1; sV[0][s + 2] = a2;
            sV[1][s]     = b0; sV[1][s + 1] = b1; sV[1][s + 2] = b2;
        }
        __syncthreads();

        // Phase 2: aligned float4 copy to global (384 vec4 per row) + 3 scalars
        const size_t base0 = ((size_t)(b * 2 + 0) * LL + l) * ROWF;
        const size_t base1 = base0 + (size_t)LL * ROWF;
        const int s0 = ao + head;   // 0 (head==0) or 4

#pragma unroll
        for (int it = 0; it < 3; it++) {
            const int t   = tid + it * 256;
            const int row = (t >= 384);
            const int v   = t - (row << 8) - (row << 7);  // t - row*384
            const float4 val = *(const float4*)&sV[row][s0 + 4 * v];
            float* gp = out + (row ? base1 : base0) + head + 4 * v;
            *(float4*)gp = val;
        }
        if (tid < 6) {
            const int row = tid / 3;
            const int j   = tid - row * 3;
            const int e   = (j < head) ? j : (1536 + j);
            out[(row ? base1 : base0) + e] = sV[row][ao + e];
        }
    }
}

extern "C" void kernel_launch(void* const* d_in, const int* in_sizes, int n_in,
                              void* d_out, int out_size) {
    const float* angles = (const float*)d_in[0];   // (32, 2, 512)
    const float* coords = (const float*)d_in[1];   // (32, 1539)
    const int*   lens   = (const int*)d_in[2];     // (32,)
    float* out = (float*)d_out;

    scan_kernel<<<BSZ, LL>>>(angles);
    emit_kernel<<<dim3(LL / 4, BSZ), 256>>>(coords, lens, out);
}